// round 4
// baseline (speedup 1.0000x reference)
#include <cuda_runtime.h>
#include <cuda_bf16.h>

#define L1N 16
#define DIN 1536
#define COUNT 8
#define L3N 64
#define BMAX 16384
#define CTA_SAMPLES 128
#define THREADS 512
#define CK 96                   // k per chunk
#define NCH (DIN / CK)          // 16
#define XST 100                 // x smem row stride (floats); %32=4 -> minimal 4-way, 16B aligned
#define HB 64

// ---- device scratch ----
__device__ float g_wsum[COUNT * DIN * L1N];   // [b][k][16]
__device__ float g_bsum[COUNT * L1N];
__device__ float g_w2p[COUNT * L3N * 32];
__device__ int   g_bh[HB * COUNT];
__device__ int   g_aoff[COUNT + 1];
__device__ int   g_order[BMAX + COUNT * CTA_SAMPLES];

// ---------------- prep (coalesced reads) + per-block histogram ----------------
__global__ void k_prep(const float* __restrict__ W1, const float* __restrict__ b1,
                       const float* __restrict__ Wf, const float* __restrict__ bf,
                       const float* __restrict__ W2, const int* __restrict__ ls,
                       int n, int hb) {
    int tid = blockIdx.x * 256 + threadIdx.x;   // grid = 192*256 = 49152
    // wsum: one float4 (along k) per thread
    {
        int idx = tid;                 // [0, 8*16*384)
        int b = idx / 6144;            // 16*384
        int r = idx - b * 6144;
        int o = r / 384;
        int k4 = r - o * 384;
        float4 a = ((const float4*)(W1 + (size_t)(b * L1N + o) * DIN))[k4];
        float4 f = ((const float4*)(Wf + (size_t)o * DIN))[k4];
        float* dst = g_wsum + (size_t)b * (DIN * L1N) + (k4 * 4) * L1N + o;
        dst[0]  = a.x + f.x;
        dst[16] = a.y + f.y;
        dst[32] = a.z + f.z;
        dst[48] = a.w + f.w;
    }
    for (int idx = tid; idx < COUNT * L3N * 32; idx += 49152) {
        int b = idx >> 11;
        int j = (idx >> 5) & 63;
        int i = idx & 31;
        g_w2p[idx] = (i < 30) ? W2[(b * L3N + j) * 30 + i] : 0.0f;
    }
    if (tid < COUNT * L1N) {
        int b = tid >> 4, o = tid & 15;
        g_bsum[tid] = b1[b * L1N + o] + bf[o];
    }
    if ((int)blockIdx.x < hb) {
        __shared__ int sh[COUNT];
        int t = threadIdx.x;
        if (t < COUNT) sh[t] = 0;
        __syncthreads();
        int i = blockIdx.x * 256 + t;
        if (i < n) {
            int b = ls[i];
            unsigned act = __activemask();
            unsigned m = __match_any_sync(act, b);
            int lane = t & 31;
            int leader = __ffs(m) - 1;
            if (lane == leader) atomicAdd(&sh[b], __popc(m));
        }
        __syncthreads();
        if (t < COUNT) g_bh[blockIdx.x * COUNT + t] = sh[t];
    }
}

// ---------------- scatter with inline scan ----------------
__global__ void k_scatter(const int* __restrict__ ls, int n, int hb) {
    __shared__ int sh[HB * COUNT];
    __shared__ int s_aoff[COUNT + 1];
    __shared__ int s_cnt[COUNT];
    __shared__ int cur[COUNT];
    int t = threadIdx.x;
    for (int i = t; i < hb * COUNT; i += 256) sh[i] = g_bh[i];
    __syncthreads();
    if (t < COUNT) {
        int tot = 0;
        for (int j = 0; j < hb; ++j) tot += sh[j * COUNT + t];
        s_cnt[t] = tot;
    }
    __syncthreads();
    if (t == 0) {
        int off = 0;
        for (int b = 0; b < COUNT; ++b) {
            s_aoff[b] = off;
            off += (s_cnt[b] + CTA_SAMPLES - 1) & ~(CTA_SAMPLES - 1);
        }
        s_aoff[COUNT] = off;
        if (blockIdx.x == 0)
            for (int b = 0; b <= COUNT; ++b) g_aoff[b] = s_aoff[b];
    }
    __syncthreads();
    if (t < COUNT) {
        int run = s_aoff[t];
        for (int j = 0; j < (int)blockIdx.x; ++j) run += sh[j * COUNT + t];
        cur[t] = run;
    }
    __syncthreads();
    if (blockIdx.x == 0) {
        for (int b = 0; b < COUNT; ++b) {
            int s = s_aoff[b] + s_cnt[b];
            int e = s_aoff[b + 1];
            for (int i = s + t; i < e; i += 256) g_order[i] = -1;
        }
    }
    int i = blockIdx.x * 256 + t;
    if (i < n) {
        int b = ls[i];
        unsigned act = __activemask();
        unsigned m = __match_any_sync(act, b);
        int lane = t & 31;
        int leader = __ffs(m) - 1;
        int rank = __popc(m & ((1u << lane) - 1u));
        int base = 0;
        if (lane == leader) base = atomicAdd(&cur[b], __popc(m));
        base = __shfl_sync(act, base, leader);
        g_order[base + rank] = i;
    }
}

// ---------------- main: 512 thr, 2 samples/lane, 8 k-slices, cp.async x staging ----------------
// smem floats: ws 24576 + w2s 2048 + bs 16 + b2 64 + wo 64 + sidx 128 + xs 2*128*100
#define SMEM_WORDS (24576 + 2048 + 16 + 64 + 64 + 128 + 2 * 128 * XST)
#define SMEM_BYTES (SMEM_WORDS * 4)

__device__ __forceinline__ unsigned smem_u32(const void* p) {
    unsigned a;
    asm("{ .reg .u64 t; cvta.to.shared.u64 t, %1; cvt.u32.u64 %0, t; }" : "=r"(a) : "l"(p));
    return a;
}

__global__ void __launch_bounds__(THREADS, 1) k_main(const float* __restrict__ x,
                                                     const float* __restrict__ b2,
                                                     const float* __restrict__ Wo,
                                                     const float* __restrict__ bo,
                                                     float* __restrict__ out) {
    extern __shared__ float sm[];
    float* ws   = sm;                   // [k][16]
    float* w2s  = ws + 24576;           // [j][32]
    float* bs   = w2s + 2048;
    float* b2s  = bs + 16;
    float* wos  = b2s + 64;
    int* sidx_s = (int*)(wos + 64);     // 128
    float* xs   = (float*)(sidx_s + 128);  // 2 * 128 * XST

    int tid = threadIdx.x;
    int base = blockIdx.x * CTA_SAMPLES;
    if (base >= g_aoff[COUNT]) return;

    int b = 0;
#pragma unroll
    for (int t = 1; t < COUNT; ++t)
        if (base >= g_aoff[t]) b = t;

    if (tid < 128) sidx_s[tid] = g_order[base + tid];
    __syncthreads();

    // ---- async x loader: thread t loads 96B of row (t>>2), quarter (t&3) per chunk ----
    int s_ld = tid >> 2, q_ld = tid & 3;
    int svl = sidx_s[s_ld];
    const char* srow = (const char*)(x + (size_t)(svl >= 0 ? svl : 0) * DIN) + q_ld * 96;
    unsigned xs_u = smem_u32(xs);
    unsigned dstA = xs_u + (unsigned)(s_ld * XST * 4 + q_ld * 96);
    unsigned bufStride = 128 * XST * 4;

    // prologue: chunks 0 and 1
#pragma unroll
    for (int j = 0; j < 6; ++j)
        asm volatile("cp.async.cg.shared.global [%0], [%1], 16;"
                     :: "r"(dstA + j * 16), "l"(srow + j * 16));
    asm volatile("cp.async.commit_group;");
#pragma unroll
    for (int j = 0; j < 6; ++j)
        asm volatile("cp.async.cg.shared.global [%0], [%1], 16;"
                     :: "r"(dstA + bufStride + j * 16), "l"(srow + 384 + j * 16));
    asm volatile("cp.async.commit_group;");

    // ---- stage weights while asyncs fly ----
    {
        const float4* src = (const float4*)(g_wsum + (size_t)b * (DIN * L1N));
        float4* dst = (float4*)ws;
#pragma unroll
        for (int r = 0; r < 12; ++r) dst[tid + r * THREADS] = src[tid + r * THREADS];
    }
    ((float4*)w2s)[tid] = ((const float4*)(g_w2p + (size_t)b * (L3N * 32)))[tid & 511];
    if (tid < 16) bs[tid] = g_bsum[b * L1N + tid];
    else if (tid >= 32 && tid < 96) b2s[tid - 32] = b2[b * L3N + (tid - 32)];
    else if (tid >= 96 && tid < 160) wos[tid - 96] = Wo[b * L3N + (tid - 96)];

    // ---- consumer mapping ----
    int wid = tid >> 5, lane = tid & 31;
    int sl = wid >> 1;            // k-slice 0..7 (12 k per chunk)
    int h  = wid & 1;
    int s0 = h * 64 + lane;
    int s1 = s0 + 32;

    unsigned long long acc[16];
#pragma unroll
    for (int i = 0; i < 16; ++i) acc[i] = 0ULL;

    const ulonglong2* wp = (const ulonglong2*)ws;

#pragma unroll 1
    for (int c = 0; c < NCH; ++c) {
        if (c + 1 < NCH) asm volatile("cp.async.wait_group 1;");
        else             asm volatile("cp.async.wait_group 0;");
        __syncthreads();

        const float* xb  = xs + (c & 1) * (128 * XST);
        const float* xr0 = xb + s0 * XST + sl * 12;
        const float* xr1 = xb + s1 * XST + sl * 12;
        int kg = c * CK + sl * 12;
#pragma unroll
        for (int kq = 0; kq < 12; kq += 4) {
            float4 xa = *(const float4*)(xr0 + kq);
            float4 xc = *(const float4*)(xr1 + kq);
#pragma unroll
            for (int t4 = 0; t4 < 4; ++t4) {
                float va = (t4 == 0) ? xa.x : (t4 == 1) ? xa.y : (t4 == 2) ? xa.z : xa.w;
                float vc = (t4 == 0) ? xc.x : (t4 == 1) ? xc.y : (t4 == 2) ? xc.z : xc.w;
                unsigned long long da, dc;
                asm("mov.b64 %0, {%1, %1};" : "=l"(da) : "f"(va));
                asm("mov.b64 %0, {%1, %1};" : "=l"(dc) : "f"(vc));
                const ulonglong2* wr = wp + (unsigned)(kg + kq + t4) * 4;
#pragma unroll
                for (int p = 0; p < 4; ++p) {
                    ulonglong2 wv = wr[p];
                    asm("fma.rn.f32x2 %0, %1, %2, %0;" : "+l"(acc[2*p])     : "l"(da), "l"(wv.x));
                    asm("fma.rn.f32x2 %0, %1, %2, %0;" : "+l"(acc[2*p+1])   : "l"(da), "l"(wv.y));
                    asm("fma.rn.f32x2 %0, %1, %2, %0;" : "+l"(acc[8+2*p])   : "l"(dc), "l"(wv.x));
                    asm("fma.rn.f32x2 %0, %1, %2, %0;" : "+l"(acc[8+2*p+1]) : "l"(dc), "l"(wv.y));
                }
            }
        }
        __syncthreads();
        if (c + 2 < NCH) {
            unsigned dst = dstA + ((c & 1) ? bufStride : 0u);
            const char* src2 = srow + (size_t)(c + 2) * 384;
#pragma unroll
            for (int j = 0; j < 6; ++j)
                asm volatile("cp.async.cg.shared.global [%0], [%1], 16;"
                             :: "r"(dst + j * 16), "l"(src2 + j * 16));
            asm volatile("cp.async.commit_group;");
        }
    }
    __syncthreads();

    // ---- 8-way k reduction through retired x buffers ----
    float* red = xs;  // [(sl*128 + s)*17 + o], 8*128*17 = 17408 floats
    {
        float* br0 = red + (sl * 128 + s0) * 17;
        float* br1 = red + (sl * 128 + s1) * 17;
#pragma unroll
        for (int p = 0; p < 8; ++p) {
            float lo, hi;
            asm("mov.b64 {%0, %1}, %2;" : "=f"(lo), "=f"(hi) : "l"(acc[p]));
            br0[2 * p] = lo; br0[2 * p + 1] = hi;
            asm("mov.b64 {%0, %1}, %2;" : "=f"(lo), "=f"(hi) : "l"(acc[8 + p]));
            br1[2 * p] = lo; br1[2 * p + 1] = hi;
        }
    }
    __syncthreads();

    // ---- tail: 4 j-groups x 128 samples ----
    int s2 = tid & 127;
    int jg = tid >> 7;
    float l1[16];
#pragma unroll
    for (int o = 0; o < 16; ++o) {
        float v = bs[o];
#pragma unroll
        for (int q = 0; q < 8; ++q) v += red[(q * 128 + s2) * 17 + o];
        l1[o] = v;
    }

    const float C = 127.0f / 128.0f;
    float lx[32];
#pragma unroll
    for (int i = 0; i < 15; ++i) {
        float v = l1[i];
        float sq = (v * v) * C;
        lx[i]      = fminf(fmaxf(sq, 0.0f), 1.0f);
        lx[15 + i] = fminf(fmaxf(v, 0.0f), 1.0f);
    }
    lx[30] = 0.0f;
    lx[31] = 0.0f;

    float l3p = 0.0f;
#pragma unroll 2
    for (int jj = 0; jj < 16; ++jj) {
        int j = jg * 16 + jj;
        float ssum = b2s[j];
        const float4* wr2 = (const float4*)(w2s + j * 32);
#pragma unroll
        for (int p = 0; p < 8; ++p) {
            float4 wv = wr2[p];
            ssum = fmaf(lx[4 * p + 0], wv.x, ssum);
            ssum = fmaf(lx[4 * p + 1], wv.y, ssum);
            ssum = fmaf(lx[4 * p + 2], wv.z, ssum);
            ssum = fmaf(lx[4 * p + 3], wv.w, ssum);
        }
        float sc = fminf(fmaxf(ssum, 0.0f), 1.0f);
        l3p = fmaf(sc, wos[j], l3p);
    }
    float* red2 = xs + 20000;  // beyond 17408, within 25600
    red2[jg * 128 + s2] = l3p;
    __syncthreads();

    if (tid < 128) {
        int sv = sidx_s[tid];
        if (sv >= 0) {
            float l3 = red2[tid] + red2[128 + tid] + red2[256 + tid] + red2[384 + tid];
            out[sv] = l3 + bo[b] + l1[15];
        }
    }
}

// ---------------- launch ----------------
extern "C" void kernel_launch(void* const* d_in, const int* in_sizes, int n_in,
                              void* d_out, int out_size) {
    const float* x  = (const float*)d_in[0];
    const int*   ls = (const int*)d_in[1];
    const float* W1 = (const float*)d_in[2];
    const float* b1 = (const float*)d_in[3];
    const float* Wf = (const float*)d_in[4];
    const float* bf = (const float*)d_in[5];
    const float* W2 = (const float*)d_in[6];
    const float* b2 = (const float*)d_in[7];
    const float* Wo = (const float*)d_in[8];
    const float* bo = (const float*)d_in[9];
    float* out = (float*)d_out;
    int n = in_sizes[1];
    if (n > BMAX) n = BMAX;

    cudaFuncSetAttribute(k_main, cudaFuncAttributeMaxDynamicSharedMemorySize, SMEM_BYTES);

    int hb = (n + 255) / 256;
    k_prep<<<192, 256>>>(W1, b1, Wf, bf, W2, ls, n, hb);
    k_scatter<<<hb, 256>>>(ls, n, hb);

    int nblk = (n + CTA_SAMPLES - 1) / CTA_SAMPLES + COUNT;
    k_main<<<nblk, THREADS, SMEM_BYTES>>>(x, b2, Wo, bo, out);
}

// round 5
// speedup vs baseline: 1.5210x; 1.5210x over previous
#include <cuda_runtime.h>
#include <cuda_bf16.h>

#define L1N 16
#define DIN 1536
#define COUNT 8
#define L3N 64
#define BMAX 16384
#define CTA_SAMPLES 128
#define THREADS 512
#define CK 64                   // k per chunk
#define NCH (DIN / CK)          // 24
#define XST 68                  // x smem row stride (floats)
#define RST 20                  // reduction row stride (floats, 16B-aligned)
#define HB 64

// ---- device scratch ----
__device__ float g_wsum[COUNT * DIN * L1N];   // [b][k][16]
__device__ float g_bsum[COUNT * L1N];
__device__ float g_w2p[COUNT * L3N * 32];
__device__ int   g_bh[HB * COUNT];
__device__ int   g_aoff[COUNT + 1];
__device__ int   g_order[BMAX + COUNT * CTA_SAMPLES];

// ---------------- prep: smem-tile transpose of W1+Wf, pad W2, histogram ----------------
// grid = 96 blocks x 256 threads. block = (bucket = blk/12, ktile = blk%12) of 128 k.
__global__ void k_prep(const float* __restrict__ W1, const float* __restrict__ b1,
                       const float* __restrict__ Wf, const float* __restrict__ bf,
                       const float* __restrict__ W2, const int* __restrict__ ls,
                       int n, int hb) {
    __shared__ float tile[16 * 132];
    int t = threadIdx.x;
    int bucket = blockIdx.x / 12;
    int kt = blockIdx.x - bucket * 12;

    // load 16 x 128 tile, coalesced along k
#pragma unroll
    for (int r = 0; r < 8; ++r) {
        int idx = t + 256 * r;          // 0..2047
        int row = idx >> 7;             // o: 0..15
        int col = idx & 127;            // k within tile
        float a = W1[(size_t)(bucket * L1N + row) * DIN + kt * 128 + col]
                + Wf[(size_t)row * DIN + kt * 128 + col];
        tile[row * 132 + col] = a;
    }
    __syncthreads();

    // write transposed [k][16], coalesced float4
    {
        float4* dst = (float4*)(g_wsum + (size_t)bucket * (DIN * L1N) + kt * 2048);
#pragma unroll
        for (int r = 0; r < 2; ++r) {
            int idx4 = t + 256 * r;     // 0..511
            int k = idx4 >> 2;
            int o4 = idx4 & 3;
            float4 v;
            v.x = tile[(4 * o4 + 0) * 132 + k];
            v.y = tile[(4 * o4 + 1) * 132 + k];
            v.z = tile[(4 * o4 + 2) * 132 + k];
            v.w = tile[(4 * o4 + 3) * 132 + k];
            dst[idx4] = v;
        }
    }

    int tidg = blockIdx.x * 256 + t;
    if (tidg < COUNT * L3N * 32) {
        int b = tidg >> 11;
        int j = (tidg >> 5) & 63;
        int i = tidg & 31;
        g_w2p[tidg] = (i < 30) ? W2[(b * L3N + j) * 30 + i] : 0.0f;
    }
    if (tidg < COUNT * L1N) {
        int b = tidg >> 4, o = tidg & 15;
        g_bsum[tidg] = b1[b * L1N + o] + bf[o];
    }
    if ((int)blockIdx.x < hb) {
        __shared__ int sh[COUNT];
        if (t < COUNT) sh[t] = 0;
        __syncthreads();
        int i = blockIdx.x * 256 + t;
        if (i < n) {
            int b = ls[i];
            unsigned act = __activemask();
            unsigned m = __match_any_sync(act, b);
            int lane = t & 31;
            int leader = __ffs(m) - 1;
            if (lane == leader) atomicAdd(&sh[b], __popc(m));
        }
        __syncthreads();
        if (t < COUNT) g_bh[blockIdx.x * COUNT + t] = sh[t];
    }
}

// ---------------- scatter with inline scan (unchanged from R3) ----------------
__global__ void k_scatter(const int* __restrict__ ls, int n, int hb) {
    __shared__ int sh[HB * COUNT];
    __shared__ int s_aoff[COUNT + 1];
    __shared__ int s_cnt[COUNT];
    __shared__ int cur[COUNT];
    int t = threadIdx.x;
    for (int i = t; i < hb * COUNT; i += 256) sh[i] = g_bh[i];
    __syncthreads();
    if (t < COUNT) {
        int tot = 0;
        for (int j = 0; j < hb; ++j) tot += sh[j * COUNT + t];
        s_cnt[t] = tot;
    }
    __syncthreads();
    if (t == 0) {
        int off = 0;
        for (int b = 0; b < COUNT; ++b) {
            s_aoff[b] = off;
            off += (s_cnt[b] + CTA_SAMPLES - 1) & ~(CTA_SAMPLES - 1);
        }
        s_aoff[COUNT] = off;
        if (blockIdx.x == 0)
            for (int b = 0; b <= COUNT; ++b) g_aoff[b] = s_aoff[b];
    }
    __syncthreads();
    if (t < COUNT) {
        int run = s_aoff[t];
        for (int j = 0; j < (int)blockIdx.x; ++j) run += sh[j * COUNT + t];
        cur[t] = run;
    }
    __syncthreads();
    if (blockIdx.x == 0) {
        for (int b = 0; b < COUNT; ++b) {
            int s = s_aoff[b] + s_cnt[b];
            int e = s_aoff[b + 1];
            for (int i = s + t; i < e; i += 256) g_order[i] = -1;
        }
    }
    int i = blockIdx.x * 256 + t;
    if (i < n) {
        int b = ls[i];
        unsigned act = __activemask();
        unsigned m = __match_any_sync(act, b);
        int lane = t & 31;
        int leader = __ffs(m) - 1;
        int rank = __popc(m & ((1u << lane) - 1u));
        int base = 0;
        if (lane == leader) base = atomicAdd(&cur[b], __popc(m));
        base = __shfl_sync(act, base, leader);
        g_order[base + rank] = i;
    }
}

// ---------------- main: 512 thr, 2 samples/lane, 8 k-slices of 8, R3 loader ----------------
// smem floats: ws 24576 + w2s 2048 + bs 16 + b2 64 + wo 64 + sidx 128 + xs 20480
#define XS_WORDS 20480
#define SMEM_WORDS (24576 + 2048 + 16 + 64 + 64 + 128 + XS_WORDS)
#define SMEM_BYTES (SMEM_WORDS * 4)

__global__ void __launch_bounds__(THREADS, 1) k_main(const float* __restrict__ x,
                                                     const float* __restrict__ b2,
                                                     const float* __restrict__ Wo,
                                                     const float* __restrict__ bo,
                                                     float* __restrict__ out) {
    extern __shared__ float sm[];
    float* ws   = sm;                   // [k][16]
    float* w2s  = ws + 24576;           // [j][32]
    float* bs   = w2s + 2048;
    float* b2s  = bs + 16;
    float* wos  = b2s + 64;
    int* sidx_s = (int*)(wos + 64);     // 128
    float* xs   = (float*)(sidx_s + 128);  // XS_WORDS

    int tid = threadIdx.x;
    int base = blockIdx.x * CTA_SAMPLES;
    if (base >= g_aoff[COUNT]) return;

    int b = 0;
#pragma unroll
    for (int t = 1; t < COUNT; ++t)
        if (base >= g_aoff[t]) b = t;

    // stage weights
    {
        const float4* src = (const float4*)(g_wsum + (size_t)b * (DIN * L1N));
        float4* dst = (float4*)ws;
#pragma unroll
        for (int r = 0; r < 12; ++r) dst[tid + r * THREADS] = src[tid + r * THREADS];
    }
    ((float4*)w2s)[tid] = ((const float4*)(g_w2p + (size_t)b * (L3N * 32)))[tid];
    if (tid < 16) bs[tid] = g_bsum[b * L1N + tid];
    else if (tid >= 32 && tid < 96) b2s[tid - 32] = b2[b * L3N + (tid - 32)];
    else if (tid >= 96 && tid < 160) wos[tid - 96] = Wo[b * L3N + (tid - 96)];
    if (tid < 128) sidx_s[tid] = g_order[base + tid];
    __syncthreads();

    // ---- loader assignment (R3-style: 16 threads/row, consecutive float4) ----
    const float4* p4[4];
    int ls_[4], lk_[4];
#pragma unroll
    for (int r = 0; r < 4; ++r) {
        int i = tid + THREADS * r;
        int s = i >> 4;                // row slot 0..127
        int k4 = i & 15;               // float4 within 64-float chunk
        ls_[r] = s; lk_[r] = k4;
        int sv = sidx_s[s];
        p4[r] = (const float4*)(x + (size_t)(sv >= 0 ? sv : 0) * DIN) + k4;
    }

    // ---- consumer mapping: 2 samples/lane, 8 k-slices of 8 ----
    int wid = tid >> 5, lane = tid & 31;
    int sl = wid & 7;                  // k-slice 0..7
    int h  = wid >> 3;                 // sample half
    int s0 = h * 64 + lane;
    int s1 = s0 + 32;

    unsigned long long acc[16];
#pragma unroll
    for (int i = 0; i < 16; ++i) acc[i] = 0ULL;

    const ulonglong2* wp = (const ulonglong2*)ws;

    float4 pf[4];
#pragma unroll
    for (int r = 0; r < 4; ++r) pf[r] = p4[r][0];

#pragma unroll 1
    for (int c = 0; c < NCH; ++c) {
        float* xb = xs + (c & 1) * (128 * XST);
#pragma unroll
        for (int r = 0; r < 4; ++r)
            *(float4*)(xb + ls_[r] * XST + lk_[r] * 4) = pf[r];
        __syncthreads();
        if (c + 1 < NCH) {
#pragma unroll
            for (int r = 0; r < 4; ++r) pf[r] = p4[r][(c + 1) * 16];
        }
        const float* xr0 = xb + s0 * XST + sl * 8;
        const float* xr1 = xb + s1 * XST + sl * 8;
        int kg = c * CK + sl * 8;
#pragma unroll
        for (int kq = 0; kq < 8; kq += 4) {
            float4 xa = *(const float4*)(xr0 + kq);
            float4 xc = *(const float4*)(xr1 + kq);
#pragma unroll
            for (int t4 = 0; t4 < 4; ++t4) {
                float va = (t4 == 0) ? xa.x : (t4 == 1) ? xa.y : (t4 == 2) ? xa.z : xa.w;
                float vc = (t4 == 0) ? xc.x : (t4 == 1) ? xc.y : (t4 == 2) ? xc.z : xc.w;
                unsigned long long da, dc;
                asm("mov.b64 %0, {%1, %1};" : "=l"(da) : "f"(va));
                asm("mov.b64 %0, {%1, %1};" : "=l"(dc) : "f"(vc));
                const ulonglong2* wr = wp + (unsigned)(kg + kq + t4) * 4;
#pragma unroll
                for (int p = 0; p < 4; ++p) {
                    ulonglong2 wv = wr[p];
                    asm("fma.rn.f32x2 %0, %1, %2, %0;" : "+l"(acc[2*p])     : "l"(da), "l"(wv.x));
                    asm("fma.rn.f32x2 %0, %1, %2, %0;" : "+l"(acc[2*p+1])   : "l"(da), "l"(wv.y));
                    asm("fma.rn.f32x2 %0, %1, %2, %0;" : "+l"(acc[8+2*p])   : "l"(dc), "l"(wv.x));
                    asm("fma.rn.f32x2 %0, %1, %2, %0;" : "+l"(acc[8+2*p+1]) : "l"(dc), "l"(wv.y));
                }
            }
        }
    }
    __syncthreads();

    // ---- 8-way k reduction (stride RST=20, 16B aligned rows) ----
    float* red = xs;  // [(sl*128 + s)*RST + o], 8*128*20 = 20480 floats
    {
        float* br0 = red + (sl * 128 + s0) * RST;
        float* br1 = red + (sl * 128 + s1) * RST;
#pragma unroll
        for (int p = 0; p < 8; ++p) {
            float lo, hi;
            asm("mov.b64 {%0, %1}, %2;" : "=f"(lo), "=f"(hi) : "l"(acc[p]));
            br0[2 * p] = lo; br0[2 * p + 1] = hi;
            asm("mov.b64 {%0, %1}, %2;" : "=f"(lo), "=f"(hi) : "l"(acc[8 + p]));
            br1[2 * p] = lo; br1[2 * p + 1] = hi;
        }
    }
    __syncthreads();

    // ---- tail: 4 j-groups x 128 samples, vectorized reduction reads ----
    int s2 = tid & 127;
    int jg = tid >> 7;
    float l1[16];
#pragma unroll
    for (int o = 0; o < 16; o += 4) {
        float4 v = *(const float4*)(bs + o);
#pragma unroll
        for (int q = 0; q < 8; ++q) {
            float4 r4 = *(const float4*)(red + (q * 128 + s2) * RST + o);
            v.x += r4.x; v.y += r4.y; v.z += r4.z; v.w += r4.w;
        }
        l1[o] = v.x; l1[o + 1] = v.y; l1[o + 2] = v.z; l1[o + 3] = v.w;
    }

    const float C = 127.0f / 128.0f;
    float lx[32];
#pragma unroll
    for (int i = 0; i < 15; ++i) {
        float v = l1[i];
        float sq = (v * v) * C;
        lx[i]      = fminf(fmaxf(sq, 0.0f), 1.0f);
        lx[15 + i] = fminf(fmaxf(v, 0.0f), 1.0f);
    }
    lx[30] = 0.0f;
    lx[31] = 0.0f;

    float l3p = 0.0f;
#pragma unroll 2
    for (int jj = 0; jj < 16; ++jj) {
        int j = jg * 16 + jj;
        float ssum = b2s[j];
        const float4* wr2 = (const float4*)(w2s + j * 32);
#pragma unroll
        for (int p = 0; p < 8; ++p) {
            float4 wv = wr2[p];
            ssum = fmaf(lx[4 * p + 0], wv.x, ssum);
            ssum = fmaf(lx[4 * p + 1], wv.y, ssum);
            ssum = fmaf(lx[4 * p + 2], wv.z, ssum);
            ssum = fmaf(lx[4 * p + 3], wv.w, ssum);
        }
        float sc = fminf(fmaxf(ssum, 0.0f), 1.0f);
        l3p = fmaf(sc, wos[j], l3p);
    }
    float* red2 = ws;   // weights no longer needed
    red2[jg * 128 + s2] = l3p;
    __syncthreads();

    if (tid < 128) {
        int sv = sidx_s[tid];
        if (sv >= 0) {
            float l3 = red2[tid] + red2[128 + tid] + red2[256 + tid] + red2[384 + tid];
            out[sv] = l3 + bo[b] + l1[15];
        }
    }
}

// ---------------- launch ----------------
extern "C" void kernel_launch(void* const* d_in, const int* in_sizes, int n_in,
                              void* d_out, int out_size) {
    const float* x  = (const float*)d_in[0];
    const int*   ls = (const int*)d_in[1];
    const float* W1 = (const float*)d_in[2];
    const float* b1 = (const float*)d_in[3];
    const float* Wf = (const float*)d_in[4];
    const float* bf = (const float*)d_in[5];
    const float* W2 = (const float*)d_in[6];
    const float* b2 = (const float*)d_in[7];
    const float* Wo = (const float*)d_in[8];
    const float* bo = (const float*)d_in[9];
    float* out = (float*)d_out;
    int n = in_sizes[1];
    if (n > BMAX) n = BMAX;

    cudaFuncSetAttribute(k_main, cudaFuncAttributeMaxDynamicSharedMemorySize, SMEM_BYTES);

    int hb = (n + 255) / 256;
    k_prep<<<96, 256>>>(W1, b1, Wf, bf, W2, ls, n, hb);
    k_scatter<<<hb, 256>>>(ls, n, hb);

    int nblk = (n + CTA_SAMPLES - 1) / CTA_SAMPLES + COUNT;
    k_main<<<nblk, THREADS, SMEM_BYTES>>>(x, b2, Wo, bo, out);
}